// round 6
// baseline (speedup 1.0000x reference)
#include <cuda_runtime.h>
#include <cuda_bf16.h>

// Problem constants (fixed by reference)
#define N_NODES 100000
#define N_EDGES 1600000
#define IN_DIM  256
#define FDIM    128

// ---------------------------------------------------------------------------
// Scratch (static device globals — no allocation). Referenced ONLY from
// device code; kernel_launch performs zero runtime API calls besides launches.
// ---------------------------------------------------------------------------
__device__ float g_h[N_NODES * FDIM];     // 51.2 MB
__device__ float g_z[N_NODES * FDIM];     // 51.2 MB
__device__ int   g_cnt[N_NODES];
__device__ int   g_rowptr[N_NODES + 1];
__device__ int   g_cursor[N_NODES];
__device__ int   g_col[N_EDGES];
__device__ float g_norm[N_NODES];
__device__ float g_deginv[N_NODES];

// ---------------------------------------------------------------------------
// CSR build.  edge_index is int32 on device (JAX x64 disabled: the reference's
// "int64" randint silently materializes as int32).  Layout: [2, E] row-major,
// so src = ei[e], dst = ei[N_EDGES + e].
// ---------------------------------------------------------------------------
__global__ void init_cnt_kernel() {
    int i = blockIdx.x * blockDim.x + threadIdx.x;
    if (i < N_NODES) g_cnt[i] = 0;
}

__global__ void count_kernel(const int* __restrict__ ei) {
    int e = blockIdx.x * blockDim.x + threadIdx.x;
    if (e < N_EDGES) {
        int d = ei[N_EDGES + e];   // dst
        if ((unsigned)d < N_NODES) atomicAdd(&g_cnt[d], 1);
    }
}

__global__ void degnorm_kernel() {
    int i = blockIdx.x * blockDim.x + threadIdx.x;
    if (i < N_NODES) {
        float deg = (float)g_cnt[i] + 1.0f;
        g_norm[i]   = rsqrtf(deg);
        g_deginv[i] = 1.0f / deg;
    }
}

// Single-block exclusive scan of g_cnt -> g_rowptr / g_cursor
__global__ void scan_kernel() {
    __shared__ int s[1024];
    const int t = threadIdx.x;
    const int CH = (N_NODES + 1023) / 1024;          // 98
    int start = t * CH;
    int end   = start + CH; if (end > N_NODES) end = N_NODES;
    if (start > N_NODES) start = N_NODES;

    int local = 0;
    for (int i = start; i < end; i++) local += g_cnt[i];
    s[t] = local;
    __syncthreads();
    // inclusive Hillis-Steele scan
    for (int d = 1; d < 1024; d <<= 1) {
        int v = (t >= d) ? s[t - d] : 0;
        __syncthreads();
        s[t] += v;
        __syncthreads();
    }
    int run = s[t] - local;                          // exclusive prefix
    for (int i = start; i < end; i++) {
        g_rowptr[i] = run;
        g_cursor[i] = run;
        run += g_cnt[i];
    }
    if (t == 1023) g_rowptr[N_NODES] = s[1023];
}

__global__ void scatter_kernel(const int* __restrict__ ei) {
    int e = blockIdx.x * blockDim.x + threadIdx.x;
    if (e < N_EDGES) {
        int src = ei[e];
        int dst = ei[N_EDGES + e];
        if ((unsigned)dst < N_NODES && (unsigned)src < N_NODES) {
            int pos = atomicAdd(&g_cursor[dst], 1);
            if ((unsigned)pos < N_EDGES) g_col[pos] = src;
        }
    }
}

// ---------------------------------------------------------------------------
// SGEMM core: C[M,128] = A[M,K] @ W[K,128] (+ bias)
// 128x128 tile, BK=8, 256 threads, 8x8 register blocking.
// ---------------------------------------------------------------------------
template <int K, bool BIAS>
__device__ __forceinline__ void gemm128_body(
    const float* __restrict__ A, const float* __restrict__ W,
    const float* __restrict__ bias, float* __restrict__ C, int M)
{
    __shared__ float As[8][128];
    __shared__ float Bs[8][128];

    const int tid = threadIdx.x;
    const int ty  = tid >> 4;        // 0..15 -> row group
    const int tx  = tid & 15;        // 0..15 -> col group
    const int m0  = blockIdx.x * 128;

    const int aRow = tid >> 1;
    const int aCol = (tid & 1) * 4;
    const int bRow = tid >> 5;
    const int bCol = (tid & 31) * 4;

    const bool aValid = (m0 + aRow) < M;
    const float* Aptr = A + (long long)(m0 + aRow) * K + aCol;

    float acc[8][8] = {};

    for (int k0 = 0; k0 < K; k0 += 8) {
        float4 av = aValid ? *(const float4*)(Aptr + k0)
                           : make_float4(0.f, 0.f, 0.f, 0.f);
        As[aCol + 0][aRow] = av.x;
        As[aCol + 1][aRow] = av.y;
        As[aCol + 2][aRow] = av.z;
        As[aCol + 3][aRow] = av.w;
        *(float4*)&Bs[bRow][bCol] = *(const float4*)(W + (k0 + bRow) * 128 + bCol);
        __syncthreads();

#pragma unroll
        for (int kk = 0; kk < 8; kk++) {
            float4 a0 = *(const float4*)&As[kk][ty * 8];
            float4 a1 = *(const float4*)&As[kk][ty * 8 + 4];
            float4 b0 = *(const float4*)&Bs[kk][tx * 8];
            float4 b1 = *(const float4*)&Bs[kk][tx * 8 + 4];
            float a[8] = {a0.x, a0.y, a0.z, a0.w, a1.x, a1.y, a1.z, a1.w};
            float b[8] = {b0.x, b0.y, b0.z, b0.w, b1.x, b1.y, b1.z, b1.w};
#pragma unroll
            for (int i = 0; i < 8; i++)
#pragma unroll
                for (int j = 0; j < 8; j++)
                    acc[i][j] = fmaf(a[i], b[j], acc[i][j]);
        }
        __syncthreads();
    }

    float bv[8];
#pragma unroll
    for (int j = 0; j < 8; j++) bv[j] = BIAS ? bias[tx * 8 + j] : 0.0f;

#pragma unroll
    for (int i = 0; i < 8; i++) {
        int row = m0 + ty * 8 + i;
        if (row < M) {
            float4 o0 = make_float4(acc[i][0] + bv[0], acc[i][1] + bv[1],
                                    acc[i][2] + bv[2], acc[i][3] + bv[3]);
            float4 o1 = make_float4(acc[i][4] + bv[4], acc[i][5] + bv[5],
                                    acc[i][6] + bv[6], acc[i][7] + bv[7]);
            *(float4*)(C + (long long)row * 128 + tx * 8)     = o0;
            *(float4*)(C + (long long)row * 128 + tx * 8 + 4) = o1;
        }
    }
}

// Stage wrappers: scratch buffers bound inside device code (no symbol API).
__global__ __launch_bounds__(256) void gemm_pre_kernel(
    const float* __restrict__ x, const float* __restrict__ Wp,
    const float* __restrict__ bp)
{
    gemm128_body<IN_DIM, true>(x, Wp, bp, g_h, N_NODES);
}

__global__ __launch_bounds__(256) void gemm_hid_kernel(
    const float* __restrict__ W)   // A = g_h, C = g_z
{
    gemm128_body<FDIM, false>(g_h, W, nullptr, g_z, N_NODES);
}

// ---------------------------------------------------------------------------
// Aggregation: out[i] = sum_{j in N(i)} norm[i]*norm[j]*z[j] + z[i]*deginv[i] + b
// One warp per node; each lane owns 4 contiguous floats (float4). z = g_z.
// ---------------------------------------------------------------------------
template <bool RELU>
__device__ __forceinline__ void agg_body(
    const float* __restrict__ bias, float* __restrict__ out)
{
    int node = (blockIdx.x * blockDim.x + threadIdx.x) >> 5;
    if (node >= N_NODES) return;
    const int lane = threadIdx.x & 31;
    const int c = lane * 4;
    const float* __restrict__ z = g_z;

    float dinv = g_deginv[node];
    float ni   = g_norm[node];
    float4 zi  = *(const float4*)(z + (long long)node * 128 + c);
    float4 bv  = *(const float4*)(bias + c);

    float4 acc;
    acc.x = fmaf(zi.x, dinv, bv.x);
    acc.y = fmaf(zi.y, dinv, bv.y);
    acc.z = fmaf(zi.z, dinv, bv.z);
    acc.w = fmaf(zi.w, dinv, bv.w);

    int p  = g_rowptr[node];
    int pe = g_rowptr[node + 1];

    // 2-wide unroll to expose memory-level parallelism
    for (; p + 2 <= pe; p += 2) {
        int j0 = g_col[p];
        int j1 = g_col[p + 1];
        float w0 = ni * g_norm[j0];
        float w1 = ni * g_norm[j1];
        float4 v0 = *(const float4*)(z + (long long)j0 * 128 + c);
        float4 v1 = *(const float4*)(z + (long long)j1 * 128 + c);
        acc.x = fmaf(w0, v0.x, acc.x); acc.x = fmaf(w1, v1.x, acc.x);
        acc.y = fmaf(w0, v0.y, acc.y); acc.y = fmaf(w1, v1.y, acc.y);
        acc.z = fmaf(w0, v0.z, acc.z); acc.z = fmaf(w1, v1.z, acc.z);
        acc.w = fmaf(w0, v0.w, acc.w); acc.w = fmaf(w1, v1.w, acc.w);
    }
    if (p < pe) {
        int j0 = g_col[p];
        float w0 = ni * g_norm[j0];
        float4 v0 = *(const float4*)(z + (long long)j0 * 128 + c);
        acc.x = fmaf(w0, v0.x, acc.x);
        acc.y = fmaf(w0, v0.y, acc.y);
        acc.z = fmaf(w0, v0.z, acc.z);
        acc.w = fmaf(w0, v0.w, acc.w);
    }

    if (RELU) {
        acc.x = fmaxf(acc.x, 0.f);
        acc.y = fmaxf(acc.y, 0.f);
        acc.z = fmaxf(acc.z, 0.f);
        acc.w = fmaxf(acc.w, 0.f);
    }
    *(float4*)(out + (long long)node * 128 + c) = acc;
}

__global__ __launch_bounds__(256) void agg_relu_kernel(
    const float* __restrict__ bias)          // g_z -> g_h, relu
{
    agg_body<true>(bias, g_h);
}

__global__ __launch_bounds__(256) void agg_out_kernel(
    const float* __restrict__ bias, float* __restrict__ out)  // g_z -> out
{
    agg_body<false>(bias, out);
}

// ---------------------------------------------------------------------------
// Launch — kernel launches ONLY (graph-capture safe, no runtime API).
// ---------------------------------------------------------------------------
extern "C" void kernel_launch(void* const* d_in, const int* in_sizes, int n_in,
                              void* d_out, int out_size)
{
    const float* x  = (const float*)d_in[0];
    const int*   ei = (const int*)d_in[1];      // int32! (JAX x64 disabled)
    const float* Wp = (const float*)d_in[2];
    const float* bp = (const float*)d_in[3];
    const float* W1 = (const float*)d_in[4];
    const float* b1 = (const float*)d_in[5];
    const float* W2 = (const float*)d_in[6];
    const float* b2 = (const float*)d_in[7];
    float*       out = (float*)d_out;

    const int NB = (N_NODES + 255) / 256;
    const int EB = (N_EDGES + 255) / 256;
    const int GB = (N_NODES + 127) / 128;      // 782 GEMM blocks
    const int AB = (N_NODES * 32 + 255) / 256; // 12500 agg blocks (1 warp/node)

    // CSR + norms
    init_cnt_kernel<<<NB, 256>>>();
    count_kernel<<<EB, 256>>>(ei);
    degnorm_kernel<<<NB, 256>>>();
    scan_kernel<<<1, 1024>>>();
    scatter_kernel<<<EB, 256>>>(ei);

    // h = x @ Wp + bp
    gemm_pre_kernel<<<GB, 256>>>(x, Wp, bp);
    // layer 1: z = h @ W1 ; h = relu(agg(z) + z*deginv + b1)
    gemm_hid_kernel<<<GB, 256>>>(W1);
    agg_relu_kernel<<<AB, 256>>>(b1);
    // layer 2: z = h @ W2 ; out = agg(z) + z*deginv + b2
    gemm_hid_kernel<<<GB, 256>>>(W2);
    agg_out_kernel<<<AB, 256>>>(b2, out);
}

// round 13
// speedup vs baseline: 2.2584x; 2.2584x over previous
#include <cuda_runtime.h>
#include <cuda_bf16.h>
#include <cstdint>

// Problem constants (fixed by reference)
#define N_NODES 100000
#define N_EDGES 1600000
#define IN_DIM  256
#define FDIM    128

#define NBLK_SCAN 391   // ceil(N_NODES/256)

// ---------------------------------------------------------------------------
// Scratch (static device globals — no allocation).
// ---------------------------------------------------------------------------
__device__ float g_h[N_NODES * FDIM];     // 51.2 MB
__device__ float g_z[N_NODES * FDIM];     // 51.2 MB
__device__ int   g_cnt[N_NODES];
__device__ int   g_rowptr[N_NODES + 1];
__device__ int   g_cursor[N_NODES];
__device__ int   g_col[N_EDGES];
__device__ float g_norm[N_NODES];
__device__ float g_deginv[N_NODES];
__device__ int   g_bsum[NBLK_SCAN];

// ---------------------------------------------------------------------------
// CSR build.  edge_index is int32 on device. Layout [2, E] row-major:
// src = ei[e], dst = ei[N_EDGES + e].
// ---------------------------------------------------------------------------
__global__ void init_cnt_kernel() {
    int i = blockIdx.x * blockDim.x + threadIdx.x;
    if (i < N_NODES) g_cnt[i] = 0;
}

__global__ void count_kernel(const int* __restrict__ ei) {
    int e = blockIdx.x * blockDim.x + threadIdx.x;
    if (e < N_EDGES) {
        int d = ei[N_EDGES + e];
        if ((unsigned)d < N_NODES) atomicAdd(&g_cnt[d], 1);
    }
}

// Phase 1: per-block sums of g_cnt (256 elements per block)
__global__ __launch_bounds__(256) void partial_sum_kernel() {
    int t = threadIdx.x;
    int i = blockIdx.x * 256 + t;
    int v = (i < N_NODES) ? g_cnt[i] : 0;
#pragma unroll
    for (int o = 16; o > 0; o >>= 1) v += __shfl_down_sync(0xffffffffu, v, o);
    __shared__ int ws[8];
    if ((t & 31) == 0) ws[t >> 5] = v;
    __syncthreads();
    if (t < 8) {
        int x = ws[t];
#pragma unroll
        for (int o = 4; o > 0; o >>= 1) x += __shfl_down_sync(0xffu, x, o);
        if (t == 0) g_bsum[blockIdx.x] = x;
    }
}

// Phase 2: exclusive scan of the 391 block sums (1 block, 512 threads)
__global__ __launch_bounds__(512) void scan_bsum_kernel() {
    __shared__ int s[512];
    int t = threadIdx.x;
    int v = (t < NBLK_SCAN) ? g_bsum[t] : 0;
    s[t] = v;
    __syncthreads();
    for (int d = 1; d < 512; d <<= 1) {
        int x = (t >= d) ? s[t - d] : 0;
        __syncthreads();
        s[t] += x;
        __syncthreads();
    }
    if (t < NBLK_SCAN) g_bsum[t] = s[t] - v;   // exclusive
}

// Phase 3: local exclusive scan + rowptr/cursor + fused degnorm
__global__ __launch_bounds__(256) void local_scan_kernel() {
    __shared__ int s[256];
    int t = threadIdx.x;
    int i = blockIdx.x * 256 + t;
    int v = (i < N_NODES) ? g_cnt[i] : 0;
    s[t] = v;
    __syncthreads();
    for (int d = 1; d < 256; d <<= 1) {
        int x = (t >= d) ? s[t - d] : 0;
        __syncthreads();
        s[t] += x;
        __syncthreads();
    }
    int incl = s[t];
    int base = g_bsum[blockIdx.x];
    if (i < N_NODES) {
        int excl = base + incl - v;
        g_rowptr[i] = excl;
        g_cursor[i] = excl;
        float deg = (float)v + 1.0f;
        g_norm[i]   = rsqrtf(deg);
        g_deginv[i] = 1.0f / deg;
        if (i == N_NODES - 1) g_rowptr[N_NODES] = base + incl;
    }
}

__global__ void scatter_kernel(const int* __restrict__ ei) {
    int e = blockIdx.x * blockDim.x + threadIdx.x;
    if (e < N_EDGES) {
        int src = ei[e];
        int dst = ei[N_EDGES + e];
        if ((unsigned)dst < N_NODES && (unsigned)src < N_NODES) {
            int pos = atomicAdd(&g_cursor[dst], 1);
            if ((unsigned)pos < N_EDGES) g_col[pos] = src;
        }
    }
}

// ---------------------------------------------------------------------------
// TF32 tensor-core GEMM: C[M,128] = A[M,K] @ W[K,128] (+ bias)
// Block tile 128x128xBK32, 256 threads = 8 warps, warp tile 32x64.
// mma.sync.aligned.m16n8k8.row.col.f32.tf32.tf32.f32
// Shared strides padded for conflict-free fragment loads:
//   As stride 36 words, Bs stride 136 words.
// ---------------------------------------------------------------------------
__device__ __forceinline__ uint32_t f2tf32(float f) {
    uint32_t u;
    asm("cvt.rna.tf32.f32 %0, %1;" : "=r"(u) : "f"(f));
    return u;
}

__device__ __forceinline__ void mma_tf32(
    float& c0, float& c1, float& c2, float& c3,
    uint32_t a0, uint32_t a1, uint32_t a2, uint32_t a3,
    uint32_t b0, uint32_t b1)
{
    asm volatile(
        "mma.sync.aligned.m16n8k8.row.col.f32.tf32.tf32.f32 "
        "{%0,%1,%2,%3}, {%4,%5,%6,%7}, {%8,%9}, {%0,%1,%2,%3};\n"
        : "+f"(c0), "+f"(c1), "+f"(c2), "+f"(c3)
        : "r"(a0), "r"(a1), "r"(a2), "r"(a3), "r"(b0), "r"(b1));
}

template <int K, bool BIAS>
__device__ __forceinline__ void gemm_tc_body(
    const float* __restrict__ A, const float* __restrict__ W,
    const float* __restrict__ bias, float* __restrict__ C, int M)
{
    __shared__ uint32_t As[128][36];   // [row][k]
    __shared__ uint32_t Bs[32][136];   // [k][n]

    const int tid  = threadIdx.x;
    const int lane = tid & 31;
    const int wid  = tid >> 5;
    const int wrow = (wid >> 1) * 32;   // 0,32,64,96
    const int wcol = (wid & 1) * 64;    // 0,64
    const int m0   = blockIdx.x * 128;

    const int q = lane >> 2;   // 0..7
    const int r = lane & 3;    // 0..3

    float c[2][8][4];
#pragma unroll
    for (int mi = 0; mi < 2; mi++)
#pragma unroll
        for (int ni = 0; ni < 8; ni++)
#pragma unroll
            for (int j = 0; j < 4; j++) c[mi][ni][j] = 0.0f;

    for (int k0 = 0; k0 < K; k0 += 32) {
        // Load A tile: 128 rows x 32 k. 256 threads x 4 float4.
#pragma unroll
        for (int p = 0; p < 4; p++) {
            int row = (tid >> 3) + p * 32;
            int kk  = (tid & 7) * 4;
            float4 v = (m0 + row < M)
                ? *(const float4*)(A + (size_t)(m0 + row) * K + k0 + kk)
                : make_float4(0.f, 0.f, 0.f, 0.f);
            As[row][kk + 0] = f2tf32(v.x);
            As[row][kk + 1] = f2tf32(v.y);
            As[row][kk + 2] = f2tf32(v.z);
            As[row][kk + 3] = f2tf32(v.w);
        }
        // Load B tile: 32 k-rows x 128 n. 256 threads x 4 float4.
#pragma unroll
        for (int p = 0; p < 4; p++) {
            int kr = (tid >> 5) + p * 8;
            int nn = (tid & 31) * 4;
            float4 v = *(const float4*)(W + (size_t)(k0 + kr) * 128 + nn);
            Bs[kr][nn + 0] = f2tf32(v.x);
            Bs[kr][nn + 1] = f2tf32(v.y);
            Bs[kr][nn + 2] = f2tf32(v.z);
            Bs[kr][nn + 3] = f2tf32(v.w);
        }
        __syncthreads();

#pragma unroll
        for (int ks = 0; ks < 4; ks++) {
            uint32_t a[2][4];
#pragma unroll
            for (int mi = 0; mi < 2; mi++) {
                int rr = wrow + mi * 16 + q;
                int kc = ks * 8 + r;
                a[mi][0] = As[rr][kc];
                a[mi][1] = As[rr + 8][kc];
                a[mi][2] = As[rr][kc + 4];
                a[mi][3] = As[rr + 8][kc + 4];
            }
            uint32_t bf[8][2];
#pragma unroll
            for (int ni = 0; ni < 8; ni++) {
                int cc = wcol + ni * 8 + q;
                int kr = ks * 8 + r;
                bf[ni][0] = Bs[kr][cc];
                bf[ni][1] = Bs[kr + 4][cc];
            }
#pragma unroll
            for (int mi = 0; mi < 2; mi++)
#pragma unroll
                for (int ni = 0; ni < 8; ni++)
                    mma_tf32(c[mi][ni][0], c[mi][ni][1], c[mi][ni][2], c[mi][ni][3],
                             a[mi][0], a[mi][1], a[mi][2], a[mi][3],
                             bf[ni][0], bf[ni][1]);
        }
        __syncthreads();
    }

    // Epilogue: c0/c1 -> (row, col..col+1), c2/c3 -> (row+8, col..col+1)
#pragma unroll
    for (int ni = 0; ni < 8; ni++) {
        int col = wcol + ni * 8 + r * 2;
        float b0v = BIAS ? bias[col]     : 0.0f;
        float b1v = BIAS ? bias[col + 1] : 0.0f;
#pragma unroll
        for (int mi = 0; mi < 2; mi++) {
            int r0 = m0 + wrow + mi * 16 + q;
            if (r0 < M) {
                float2 o = make_float2(c[mi][ni][0] + b0v, c[mi][ni][1] + b1v);
                *(float2*)(C + (size_t)r0 * 128 + col) = o;
            }
            int r1 = r0 + 8;
            if (r1 < M) {
                float2 o = make_float2(c[mi][ni][2] + b0v, c[mi][ni][3] + b1v);
                *(float2*)(C + (size_t)r1 * 128 + col) = o;
            }
        }
    }
}

__global__ __launch_bounds__(256) void gemm_pre_kernel(
    const float* __restrict__ x, const float* __restrict__ Wp,
    const float* __restrict__ bp)
{
    gemm_tc_body<IN_DIM, true>(x, Wp, bp, g_h, N_NODES);
}

__global__ __launch_bounds__(256) void gemm_hid_kernel(
    const float* __restrict__ W)   // A = g_h, C = g_z
{
    gemm_tc_body<FDIM, false>(g_h, W, nullptr, g_z, N_NODES);
}

// ---------------------------------------------------------------------------
// Aggregation: out[i] = sum_{j in N(i)} norm[i]*norm[j]*z[j] + z[i]*deginv[i] + b
// One warp per node; each lane owns 4 contiguous floats (float4). z = g_z.
// ---------------------------------------------------------------------------
template <bool RELU>
__device__ __forceinline__ void agg_body(
    const float* __restrict__ bias, float* __restrict__ out)
{
    int node = (blockIdx.x * blockDim.x + threadIdx.x) >> 5;
    if (node >= N_NODES) return;
    const int lane = threadIdx.x & 31;
    const int c = lane * 4;
    const float* __restrict__ z = g_z;

    float dinv = g_deginv[node];
    float ni   = g_norm[node];
    float4 zi  = *(const float4*)(z + (size_t)node * 128 + c);
    float4 bv  = *(const float4*)(bias + c);

    float4 acc;
    acc.x = fmaf(zi.x, dinv, bv.x);
    acc.y = fmaf(zi.y, dinv, bv.y);
    acc.z = fmaf(zi.z, dinv, bv.z);
    acc.w = fmaf(zi.w, dinv, bv.w);

    int p  = g_rowptr[node];
    int pe = g_rowptr[node + 1];

    for (; p + 2 <= pe; p += 2) {
        int j0 = g_col[p];
        int j1 = g_col[p + 1];
        float w0 = ni * g_norm[j0];
        float w1 = ni * g_norm[j1];
        float4 v0 = *(const float4*)(z + (size_t)j0 * 128 + c);
        float4 v1 = *(const float4*)(z + (size_t)j1 * 128 + c);
        acc.x = fmaf(w0, v0.x, acc.x); acc.x = fmaf(w1, v1.x, acc.x);
        acc.y = fmaf(w0, v0.y, acc.y); acc.y = fmaf(w1, v1.y, acc.y);
        acc.z = fmaf(w0, v0.z, acc.z); acc.z = fmaf(w1, v1.z, acc.z);
        acc.w = fmaf(w0, v0.w, acc.w); acc.w = fmaf(w1, v1.w, acc.w);
    }
    if (p < pe) {
        int j0 = g_col[p];
        float w0 = ni * g_norm[j0];
        float4 v0 = *(const float4*)(z + (size_t)j0 * 128 + c);
        acc.x = fmaf(w0, v0.x, acc.x);
        acc.y = fmaf(w0, v0.y, acc.y);
        acc.z = fmaf(w0, v0.z, acc.z);
        acc.w = fmaf(w0, v0.w, acc.w);
    }

    if (RELU) {
        acc.x = fmaxf(acc.x, 0.f);
        acc.y = fmaxf(acc.y, 0.f);
        acc.z = fmaxf(acc.z, 0.f);
        acc.w = fmaxf(acc.w, 0.f);
    }
    *(float4*)(out + (size_t)node * 128 + c) = acc;
}

__global__ __launch_bounds__(256) void agg_relu_kernel(
    const float* __restrict__ bias)          // g_z -> g_h, relu
{
    agg_body<true>(bias, g_h);
}

__global__ __launch_bounds__(256) void agg_out_kernel(
    const float* __restrict__ bias, float* __restrict__ out)  // g_z -> out
{
    agg_body<false>(bias, out);
}

// ---------------------------------------------------------------------------
// Launch — kernel launches ONLY (graph-capture safe).
// ---------------------------------------------------------------------------
extern "C" void kernel_launch(void* const* d_in, const int* in_sizes, int n_in,
                              void* d_out, int out_size)
{
    const float* x  = (const float*)d_in[0];
    const int*   ei = (const int*)d_in[1];      // int32 (JAX x64 disabled)
    const float* Wp = (const float*)d_in[2];
    const float* bp = (const float*)d_in[3];
    const float* W1 = (const float*)d_in[4];
    const float* b1 = (const float*)d_in[5];
    const float* W2 = (const float*)d_in[6];
    const float* b2 = (const float*)d_in[7];
    float*       out = (float*)d_out;

    const int NB = (N_NODES + 255) / 256;      // 391
    const int EB = (N_EDGES + 255) / 256;
    const int GB = (N_NODES + 127) / 128;      // 782 GEMM blocks
    const int AB = (N_NODES * 32 + 255) / 256; // 12500 agg blocks

    // CSR + norms (parallel 3-phase scan, degnorm fused into phase 3)
    init_cnt_kernel<<<NB, 256>>>();
    count_kernel<<<EB, 256>>>(ei);
    partial_sum_kernel<<<NBLK_SCAN, 256>>>();
    scan_bsum_kernel<<<1, 512>>>();
    local_scan_kernel<<<NBLK_SCAN, 256>>>();
    scatter_kernel<<<EB, 256>>>(ei);

    // h = x @ Wp + bp
    gemm_pre_kernel<<<GB, 256>>>(x, Wp, bp);
    // layer 1: z = h @ W1 ; h = relu(agg(z) + z*deginv + b1)
    gemm_hid_kernel<<<GB, 256>>>(W1);
    agg_relu_kernel<<<AB, 256>>>(b1);
    // layer 2: z = h @ W2 ; out = agg(z) + z*deginv + b2
    gemm_hid_kernel<<<GB, 256>>>(W2);
    agg_out_kernel<<<AB, 256>>>(b2, out);
}